// round 1
// baseline (speedup 1.0000x reference)
#include <cuda_runtime.h>
#include <math_constants.h>

#define EMBED   1024
#define NH      16
#define HD      64
#define CACHE   16384
#define NB1     512               // blocks in fused shift+attention kernel
#define ROWS_PER (CACHE / NB1)    // 32
#define ISPLIT  32
#define IPB     (EMBED / ISPLIT)  // 32 rows of W per split block

// ---------------- device scratch (no allocations allowed) ----------------
__device__ __align__(16) float g_qkv[3 * EMBED];          // [0]=q raw, [1]=k_i, [2]=v_i (all with bias)
__device__ __align__(16) float g_pm[NB1 * NH];            // per-block per-head running max
__device__ __align__(16) float g_pl[NB1 * NH];            // per-block per-head sum-exp
__device__ __align__(16) float g_pacc[NB1 * NH * HD];     // per-block per-head weighted-V accum
__device__ __align__(16) float g_values[EMBED];           // attention output (pre-Wo)

// ---------------- K_init: reset accumulators each replay ----------------
__global__ void init_kernel(const float* __restrict__ bq, const float* __restrict__ bk,
                            const float* __restrict__ bv, const float* __restrict__ bo,
                            float* __restrict__ out) {
    int i = blockIdx.x * blockDim.x + threadIdx.x;   // 0..4095
    if (i < EMBED)               g_qkv[i]             = bq[i];
    else if (i < 2 * EMBED)      g_qkv[i]             = bk[i - EMBED];
    else if (i < 3 * EMBED)      g_qkv[i]             = bv[i - 2 * EMBED];
    else                         out[i - 3 * EMBED]   = bo[i - 3 * EMBED];
}

// ---------------- K0: q/k/v projections (split-K GEMV, atomic combine) ----------------
__global__ __launch_bounds__(256) void qkv_kernel(const float* __restrict__ x,
                                                  const float* __restrict__ Wq,
                                                  const float* __restrict__ Wk,
                                                  const float* __restrict__ Wv) {
    const int mat = blockIdx.x;                     // 0=q,1=k,2=v
    const int j   = blockIdx.y * 256 + threadIdx.x; // output column
    const int i0  = blockIdx.z * IPB;               // input-row slice
    const float* W = (mat == 0) ? Wq : (mat == 1) ? Wk : Wv;

    __shared__ float xs[IPB];
    if (threadIdx.x < IPB) xs[threadIdx.x] = x[i0 + threadIdx.x];
    __syncthreads();

    float acc = 0.f;
#pragma unroll 8
    for (int i = 0; i < IPB; ++i)
        acc += xs[i] * W[(size_t)(i0 + i) * EMBED + j];
    atomicAdd(&g_qkv[mat * EMBED + j], acc);
}

// ---------------- K1: fused cache-shift copy + flash-attention partial ----------------
__device__ __forceinline__ void load_row(int t, int tid,
                                         const float4* __restrict__ cv,
                                         const float4* __restrict__ ck,
                                         const float4* __restrict__ vi,
                                         const float4* __restrict__ ki,
                                         float4& v, float4& k) {
    if (t == CACHE - 1) { v = vi[tid]; k = ki[tid]; }
    else {
        v = cv[(size_t)(t + 1) * 256 + tid];
        k = ck[(size_t)(t + 1) * 256 + tid];
    }
}

__global__ __launch_bounds__(256) void shift_attn_kernel(const float* __restrict__ cache,
                                                         float* __restrict__ out) {
    const int tid = threadIdx.x;        // 0..255: covers one 1024-float row as float4
    const int h   = tid >> 4;           // head 0..15
    const int sub = tid & 15;           // float4 index within head (4 dims)
    const int t0  = blockIdx.x * ROWS_PER;

    const float4* cv = reinterpret_cast<const float4*>(cache);
    const float4* ck = reinterpret_cast<const float4*>(cache + (size_t)CACHE * EMBED);
    const float4* vi = reinterpret_cast<const float4*>(&g_qkv[2 * EMBED]);
    const float4* ki = reinterpret_cast<const float4*>(&g_qkv[1 * EMBED]);
    float4* outv = reinterpret_cast<float4*>(out + EMBED);
    float4* outk = reinterpret_cast<float4*>(out + EMBED + (size_t)CACHE * EMBED);

    const float4 q4 = *reinterpret_cast<const float4*>(&g_qkv[h * HD + sub * 4]);

    float4 acc = make_float4(0.f, 0.f, 0.f, 0.f);
    float  m   = -CUDART_INF_F;
    float  l   = 0.f;

    // software pipeline: prefetch next row before this row's barrier
    float4 v4, k4;
    load_row(t0, tid, cv, ck, vi, ki, v4, k4);

    for (int r = 0; r < ROWS_PER; ++r) {
        const int t = t0 + r;
        float4 vn, kn;
        if (r + 1 < ROWS_PER) load_row(t + 1, tid, cv, ck, vi, ki, vn, kn);

        // shifted-cache write
        outv[(size_t)t * 256 + tid] = v4;
        outk[(size_t)t * 256 + tid] = k4;

        // row-valid mask: any nonzero v element in the whole 1024-float row
        int nz = (v4.x != 0.f) | (v4.y != 0.f) | (v4.z != 0.f) | (v4.w != 0.f);
        int valid = __syncthreads_or(nz);

        // per-head logit: 64-dim dot reduced over the 16-lane head group
        float pd = q4.x * k4.x + q4.y * k4.y + q4.z * k4.z + q4.w * k4.w;
        pd += __shfl_xor_sync(0xffffffffu, pd, 1);
        pd += __shfl_xor_sync(0xffffffffu, pd, 2);
        pd += __shfl_xor_sync(0xffffffffu, pd, 4);
        pd += __shfl_xor_sync(0xffffffffu, pd, 8);

        if (valid) {
            float logit = pd * 0.125f;               // / sqrt(64)
            float mnew  = fmaxf(m, logit);
            float corr  = __expf(m - mnew);          // 0 when m == -inf
            float p     = __expf(logit - mnew);
            l = l * corr + p;
            acc.x = acc.x * corr + p * v4.x;
            acc.y = acc.y * corr + p * v4.y;
            acc.z = acc.z * corr + p * v4.z;
            acc.w = acc.w * corr + p * v4.w;
            m = mnew;
        }
        v4 = vn; k4 = kn;
    }

    const int ph = blockIdx.x * NH + h;
    if (sub == 0) { g_pm[ph] = m; g_pl[ph] = l; }
    reinterpret_cast<float4*>(g_pacc)[ph * 16 + sub] = acc;
}

// ---------------- K2: combine per-block flash partials ----------------
__global__ __launch_bounds__(256) void reduce_kernel() {
    const int h   = blockIdx.x;
    const int tid = threadIdx.x;
    __shared__ float sm[256];

    // global max over blocks
    float mloc = -CUDART_INF_F;
    for (int b = tid; b < NB1; b += 256) mloc = fmaxf(mloc, g_pm[b * NH + h]);
    sm[tid] = mloc; __syncthreads();
    for (int s = 128; s > 0; s >>= 1) { if (tid < s) sm[tid] = fmaxf(sm[tid], sm[tid + s]); __syncthreads(); }
    const float mg = sm[0]; __syncthreads();

    // global sum-exp
    float lloc = 0.f;
    for (int b = tid; b < NB1; b += 256) lloc += g_pl[b * NH + h] * __expf(g_pm[b * NH + h] - mg);
    sm[tid] = lloc; __syncthreads();
    for (int s = 128; s > 0; s >>= 1) { if (tid < s) sm[tid] += sm[tid + s]; __syncthreads(); }
    const float lg = sm[0]; __syncthreads();

    // accumulator combine: 4 block-strides x 64 dims
    const int s4 = tid >> 6;   // 0..3
    const int d  = tid & 63;
    float a = 0.f;
    for (int b = s4; b < NB1; b += 4)
        a += g_pacc[(size_t)(b * NH + h) * HD + d] * __expf(g_pm[b * NH + h] - mg);
    sm[tid] = a; __syncthreads();
    if (tid < 64) {
        float r = sm[tid] + sm[tid + 64] + sm[tid + 128] + sm[tid + 192];
        g_values[h * HD + tid] = r / lg;
    }
}

// ---------------- K3: output projection (split-K GEMV, atomic into d_out) ----------------
__global__ __launch_bounds__(256) void out_kernel(const float* __restrict__ Wo,
                                                  float* __restrict__ out) {
    const int j  = blockIdx.x * 256 + threadIdx.x;
    const int i0 = blockIdx.y * IPB;
    __shared__ float xs[IPB];
    if (threadIdx.x < IPB) xs[threadIdx.x] = g_values[i0 + threadIdx.x];
    __syncthreads();
    float acc = 0.f;
#pragma unroll 8
    for (int i = 0; i < IPB; ++i)
        acc += xs[i] * Wo[(size_t)(i0 + i) * EMBED + j];
    atomicAdd(&out[j], acc);
}

// ---------------- launch ----------------
extern "C" void kernel_launch(void* const* d_in, const int* in_sizes, int n_in,
                              void* d_out, int out_size) {
    const float* x     = (const float*)d_in[0];
    const float* cache = (const float*)d_in[1];
    const float* Wv    = (const float*)d_in[2];
    const float* bv    = (const float*)d_in[3];
    const float* Wq    = (const float*)d_in[4];
    const float* bq    = (const float*)d_in[5];
    const float* Wk    = (const float*)d_in[6];
    const float* bk    = (const float*)d_in[7];
    const float* Wo    = (const float*)d_in[8];
    const float* bo    = (const float*)d_in[9];
    float* out = (float*)d_out;

    init_kernel<<<16, 256>>>(bq, bk, bv, bo, out);
    qkv_kernel<<<dim3(3, 4, ISPLIT), 256>>>(x, Wq, Wk, Wv);
    shift_attn_kernel<<<NB1, 256>>>(cache, out);
    reduce_kernel<<<NH, 256>>>();
    out_kernel<<<dim3(4, ISPLIT), 256>>>(Wo, out);
}

// round 3
// speedup vs baseline: 1.1662x; 1.1662x over previous
#include <cuda_runtime.h>
#include <math_constants.h>

#define EMBED   1024
#define NH      16
#define HD      64
#define CACHE   16384
#define NB1     512               // blocks in fused shift+attention kernel
#define ROWS_PER (CACHE / NB1)    // 32
#define ISPLIT  32
#define IPB     (EMBED / ISPLIT)  // 32 rows of W per split block

// ---------------- device scratch (no allocations allowed) ----------------
__device__ __align__(16) float g_qkv[3 * EMBED];          // [0]=q, [1]=k_i, [2]=v_i (with bias)
__device__ __align__(16) float g_pm[NB1 * NH];            // per-block per-head running max
__device__ __align__(16) float g_pl[NB1 * NH];            // per-block per-head sum-exp
__device__ __align__(16) float g_sc[NB1 * NH];            // per-block per-head softmax scale
__device__ __align__(16) float g_pacc[NB1 * NH * HD];     // per-block per-head weighted-V accum
__device__ __align__(16) float g_values[EMBED];           // attention output (pre-Wo, pre-1/l)
__device__ __align__(16) float g_linv[NH];                // 1 / sum-exp per head

// ---------------- K_init: reset accumulators each replay ----------------
__global__ void init_kernel(const float* __restrict__ bq, const float* __restrict__ bk,
                            const float* __restrict__ bv, const float* __restrict__ bo,
                            float* __restrict__ out) {
    int i = blockIdx.x * blockDim.x + threadIdx.x;   // 0..5119
    if (i < EMBED)               g_qkv[i]             = bq[i];
    else if (i < 2 * EMBED)      g_qkv[i]             = bk[i - EMBED];
    else if (i < 3 * EMBED)      g_qkv[i]             = bv[i - 2 * EMBED];
    else if (i < 4 * EMBED)      out[i - 3 * EMBED]   = bo[i - 3 * EMBED];
    else                         g_values[i - 4 * EMBED] = 0.f;
}

// ---------------- K0: q/k/v projections (split-K GEMV, atomic combine) ----------------
__global__ __launch_bounds__(256) void qkv_kernel(const float* __restrict__ x,
                                                  const float* __restrict__ Wq,
                                                  const float* __restrict__ Wk,
                                                  const float* __restrict__ Wv) {
    const int mat = blockIdx.x;                     // 0=q,1=k,2=v
    const int j   = blockIdx.y * 256 + threadIdx.x; // output column
    const int i0  = blockIdx.z * IPB;               // input-row slice
    const float* W = (mat == 0) ? Wq : (mat == 1) ? Wk : Wv;

    __shared__ float xs[IPB];
    if (threadIdx.x < IPB) xs[threadIdx.x] = x[i0 + threadIdx.x];
    __syncthreads();

    float acc = 0.f;
#pragma unroll 8
    for (int i = 0; i < IPB; ++i)
        acc += xs[i] * W[(size_t)(i0 + i) * EMBED + j];
    atomicAdd(&g_qkv[mat * EMBED + j], acc);
}

// ---------------- K1: fused cache-shift copy + flash-attention partial ----------------
__device__ __forceinline__ void load_row(int t, int tid,
                                         const float4* __restrict__ cv,
                                         const float4* __restrict__ ck,
                                         const float4* __restrict__ vi,
                                         const float4* __restrict__ ki,
                                         float4& v, float4& k) {
    if (t == CACHE - 1) { v = vi[tid]; k = ki[tid]; }
    else {
        v = cv[(size_t)(t + 1) * 256 + tid];
        k = ck[(size_t)(t + 1) * 256 + tid];
    }
}

__global__ __launch_bounds__(256) void shift_attn_kernel(const float* __restrict__ cache,
                                                         float* __restrict__ out) {
    const int tid = threadIdx.x;        // 0..255: covers one 1024-float row as float4
    const int h   = tid >> 4;           // head 0..15
    const int sub = tid & 15;           // float4 index within head (4 dims)
    const int t0  = blockIdx.x * ROWS_PER;

    const float4* cv = reinterpret_cast<const float4*>(cache);
    const float4* ck = reinterpret_cast<const float4*>(cache + (size_t)CACHE * EMBED);
    const float4* vi = reinterpret_cast<const float4*>(&g_qkv[2 * EMBED]);
    const float4* ki = reinterpret_cast<const float4*>(&g_qkv[1 * EMBED]);
    float4* outv = reinterpret_cast<float4*>(out + EMBED);
    float4* outk = reinterpret_cast<float4*>(out + EMBED + (size_t)CACHE * EMBED);

    const float4 q4 = *reinterpret_cast<const float4*>(&g_qkv[h * HD + sub * 4]);

    float4 acc = make_float4(0.f, 0.f, 0.f, 0.f);
    float  m   = -CUDART_INF_F;
    float  l   = 0.f;

    // software pipeline: prefetch next row before this row's barrier
    float4 v4, k4;
    load_row(t0, tid, cv, ck, vi, ki, v4, k4);

    for (int r = 0; r < ROWS_PER; ++r) {
        const int t = t0 + r;
        float4 vn, kn;
        if (r + 1 < ROWS_PER) load_row(t + 1, tid, cv, ck, vi, ki, vn, kn);

        // shifted-cache write
        outv[(size_t)t * 256 + tid] = v4;
        outk[(size_t)t * 256 + tid] = k4;

        // row-valid mask: any nonzero v element in the whole 1024-float row
        int nz = (v4.x != 0.f) | (v4.y != 0.f) | (v4.z != 0.f) | (v4.w != 0.f);
        int valid = __syncthreads_or(nz);

        // per-head logit: 64-dim dot reduced over the 16-lane head group
        float pd = q4.x * k4.x + q4.y * k4.y + q4.z * k4.z + q4.w * k4.w;
        pd += __shfl_xor_sync(0xffffffffu, pd, 1);
        pd += __shfl_xor_sync(0xffffffffu, pd, 2);
        pd += __shfl_xor_sync(0xffffffffu, pd, 4);
        pd += __shfl_xor_sync(0xffffffffu, pd, 8);

        if (valid) {
            float logit = pd * 0.125f;               // / sqrt(64)
            float mnew  = fmaxf(m, logit);
            float corr  = __expf(m - mnew);          // 0 when m == -inf
            float p     = __expf(logit - mnew);
            l = l * corr + p;
            acc.x = acc.x * corr + p * v4.x;
            acc.y = acc.y * corr + p * v4.y;
            acc.z = acc.z * corr + p * v4.z;
            acc.w = acc.w * corr + p * v4.w;
            m = mnew;
        }
        v4 = vn; k4 = kn;
    }

    const int ph = blockIdx.x * NH + h;
    if (sub == 0) { g_pm[ph] = m; g_pl[ph] = l; }
    reinterpret_cast<float4*>(g_pacc)[ph * 16 + sub] = acc;
}

// ---------------- K2a: per-head softmax scales (1 block, warp per head) ----------------
__global__ __launch_bounds__(512) void scale_kernel() {
    const int h    = threadIdx.x >> 5;   // warp = head
    const int lane = threadIdx.x & 31;

    float pm[16], pl[16];
    float mloc = -CUDART_INF_F;
#pragma unroll
    for (int i = 0; i < 16; ++i) {
        const int b = i * 32 + lane;
        pm[i] = g_pm[b * NH + h];
        pl[i] = g_pl[b * NH + h];
        mloc  = fmaxf(mloc, pm[i]);
    }
#pragma unroll
    for (int o = 16; o; o >>= 1) mloc = fmaxf(mloc, __shfl_xor_sync(0xffffffffu, mloc, o));

    float lsum = 0.f;
#pragma unroll
    for (int i = 0; i < 16; ++i) {
        const int b  = i * 32 + lane;
        const float sc = __expf(pm[i] - mloc);
        g_sc[b * NH + h] = sc;
        lsum += pl[i] * sc;
    }
#pragma unroll
    for (int o = 16; o; o >>= 1) lsum += __shfl_xor_sync(0xffffffffu, lsum, o);
    if (lane == 0) g_linv[h] = 1.f / lsum;
}

// ---------------- K2b: wide partial-accumulator combine (float4 per thread) ----------------
__global__ __launch_bounds__(256) void combine_kernel() {
    const int h     = blockIdx.x;        // head
    const int chunk = blockIdx.y;        // 0..3: 128 source blocks each
    const int f4    = threadIdx.x & 15;  // float4 index within head (4 dims)
    const int s     = threadIdx.x >> 4;  // 0..15: block sub-stride

    __shared__ float  scs[128];
    __shared__ float4 red[256];
    if (threadIdx.x < 128) scs[threadIdx.x] = g_sc[(chunk * 128 + threadIdx.x) * NH + h];
    __syncthreads();

    const float4* pa = reinterpret_cast<const float4*>(g_pacc);
    float4 a = make_float4(0.f, 0.f, 0.f, 0.f);
#pragma unroll
    for (int i = 0; i < 8; ++i) {
        const int bl = s * 8 + i;                    // 0..127
        const int b  = chunk * 128 + bl;
        const float sc = scs[bl];
        const float4 p = pa[(size_t)(b * NH + h) * 16 + f4];
        a.x += p.x * sc; a.y += p.y * sc; a.z += p.z * sc; a.w += p.w * sc;
    }
    red[threadIdx.x] = a;
    __syncthreads();
    // tree-reduce the 16 sub-strides for each f4
    for (int step = 8; step; step >>= 1) {
        if ((threadIdx.x >> 4) < step) {
            float4 o = red[threadIdx.x + step * 16];
            float4 mval = red[threadIdx.x];
            mval.x += o.x; mval.y += o.y; mval.z += o.z; mval.w += o.w;
            red[threadIdx.x] = mval;
        }
        __syncthreads();
    }
    if (threadIdx.x < 16) {
        const float4 r = red[threadIdx.x];
        float* dst = &g_values[h * HD + threadIdx.x * 4];
        atomicAdd(dst + 0, r.x);
        atomicAdd(dst + 1, r.y);
        atomicAdd(dst + 2, r.z);
        atomicAdd(dst + 3, r.w);
    }
}

// ---------------- K3: output projection (split-K GEMV, atomic into d_out) ----------------
__global__ __launch_bounds__(256) void out_kernel(const float* __restrict__ Wo,
                                                  float* __restrict__ out) {
    const int j  = blockIdx.x * 256 + threadIdx.x;
    const int i0 = blockIdx.y * IPB;
    __shared__ float xs[IPB];
    if (threadIdx.x < IPB) {
        const int src = i0 + threadIdx.x;
        xs[threadIdx.x] = g_values[src] * g_linv[src >> 6];   // fold 1/l here
    }
    __syncthreads();
    float acc = 0.f;
#pragma unroll 8
    for (int i = 0; i < IPB; ++i)
        acc += xs[i] * Wo[(size_t)(i0 + i) * EMBED + j];
    atomicAdd(&out[j], acc);
}

// ---------------- launch ----------------
extern "C" void kernel_launch(void* const* d_in, const int* in_sizes, int n_in,
                              void* d_out, int out_size) {
    const float* x     = (const float*)d_in[0];
    const float* cache = (const float*)d_in[1];
    const float* Wv    = (const float*)d_in[2];
    const float* bv    = (const float*)d_in[3];
    const float* Wq    = (const float*)d_in[4];
    const float* bq    = (const float*)d_in[5];
    const float* Wk    = (const float*)d_in[6];
    const float* bk    = (const float*)d_in[7];
    const float* Wo    = (const float*)d_in[8];
    const float* bo    = (const float*)d_in[9];
    float* out = (float*)d_out;

    init_kernel<<<20, 256>>>(bq, bk, bv, bo, out);
    qkv_kernel<<<dim3(3, 4, ISPLIT), 256>>>(x, Wq, Wk, Wv);
    shift_attn_kernel<<<NB1, 256>>>(cache, out);
    scale_kernel<<<1, 512>>>();
    combine_kernel<<<dim3(NH, 4), 256>>>();
    out_kernel<<<dim3(4, ISPLIT), 256>>>(Wo, out);
}

// round 6
// speedup vs baseline: 1.3347x; 1.1445x over previous
#include <cuda_runtime.h>
#include <math_constants.h>

#define EMBED   1024
#define NH      16
#define HD      64
#define CACHE   16384
#define NBLK    148               // one block per SM, grid-stride over rows
#define WPB     8                 // warps per block
#define NW      (NBLK * WPB)      // total warps = 1184
#define ISPLIT  32
#define IPB     (EMBED / ISPLIT)  // 32 rows of W per split block

// ---------------- device scratch (no allocations allowed) ----------------
__device__ __align__(16) float g_qkv[3 * EMBED];   // [0]=q, [1]=k_i, [2]=v_i (with bias)
__device__ __align__(16) float g_values[EMBED];    // unnormalized attention output
__device__ __align__(16) float g_l[NH];            // sum-exp per head

// ---------------- K_init: reset accumulators each replay ----------------
__global__ void init_kernel(const float* __restrict__ bq, const float* __restrict__ bk,
                            const float* __restrict__ bv, const float* __restrict__ bo,
                            float* __restrict__ out) {
    int i = blockIdx.x * blockDim.x + threadIdx.x;   // 0..5375
    if (i < EMBED)               g_qkv[i]               = bq[i];
    else if (i < 2 * EMBED)      g_qkv[i]               = bk[i - EMBED];
    else if (i < 3 * EMBED)      g_qkv[i]               = bv[i - 2 * EMBED];
    else if (i < 4 * EMBED)      out[i - 3 * EMBED]     = bo[i - 3 * EMBED];
    else if (i < 5 * EMBED)      g_values[i - 4 * EMBED] = 0.f;
    else if (i < 5 * EMBED + NH) g_l[i - 5 * EMBED]     = 0.f;
}

// ---------------- K0: q/k/v projections (split-K GEMV, atomic combine) ----------------
__global__ __launch_bounds__(256) void qkv_kernel(const float* __restrict__ x,
                                                  const float* __restrict__ Wq,
                                                  const float* __restrict__ Wk,
                                                  const float* __restrict__ Wv) {
    const int mat = blockIdx.x;                     // 0=q,1=k,2=v
    const int j   = blockIdx.y * 256 + threadIdx.x; // output column
    const int i0  = blockIdx.z * IPB;               // input-row slice
    const float* W = (mat == 0) ? Wq : (mat == 1) ? Wk : Wv;

    __shared__ float xs[IPB];
    if (threadIdx.x < IPB) xs[threadIdx.x] = x[i0 + threadIdx.x];
    __syncthreads();

    float acc = 0.f;
#pragma unroll 8
    for (int i = 0; i < IPB; ++i)
        acc += xs[i] * W[(size_t)(i0 + i) * EMBED + j];
    atomicAdd(&g_qkv[mat * EMBED + j], acc);
}

// ---------------- K1: warp-per-row fused shift + attention (no block barriers) ----------------
__global__ __launch_bounds__(256, 1) void shift_attn_kernel(const float* __restrict__ cache,
                                                            float* __restrict__ out) {
    const int lane = threadIdx.x & 31;
    const int wid  = threadIdx.x >> 5;              // warp in block 0..7
    const int gw   = blockIdx.x * WPB + wid;        // global warp 0..1183

    const float4* cv = reinterpret_cast<const float4*>(cache);
    const float4* ck = reinterpret_cast<const float4*>(cache + (size_t)CACHE * EMBED);
    const float4* qf = reinterpret_cast<const float4*>(g_qkv);              // 256 float4
    const float4* kf = reinterpret_cast<const float4*>(g_qkv + EMBED);
    const float4* vf = reinterpret_cast<const float4*>(g_qkv + 2 * EMBED);
    float4* outv = reinterpret_cast<float4*>(out + EMBED);
    float4* outk = reinterpret_cast<float4*>(out + EMBED + (size_t)CACHE * EMBED);

    // q for this lane's 8 head-chunks (row-invariant; preload once)
    float4 q4[8];
#pragma unroll
    for (int j = 0; j < 8; ++j) q4[j] = qf[lane + 32 * j];

    float4 acc[8];
#pragma unroll
    for (int j = 0; j < 8; ++j) acc[j] = make_float4(0.f, 0.f, 0.f, 0.f);
    float lsum[8];
#pragma unroll
    for (int j = 0; j < 8; ++j) lsum[j] = 0.f;

    for (int t = gw; t < CACHE; t += NW) {
        float4 v4[8], k4[8];
        if (t == CACHE - 1) {
#pragma unroll
            for (int j = 0; j < 8; ++j) {
                v4[j] = vf[lane + 32 * j];
                k4[j] = kf[lane + 32 * j];
            }
        } else {
            const size_t base = (size_t)(t + 1) * 256;
#pragma unroll
            for (int j = 0; j < 8; ++j) {
                v4[j] = cv[base + lane + 32 * j];
                k4[j] = ck[base + lane + 32 * j];
            }
        }

        // shifted-cache writes (warp covers whole row)
        const size_t ob = (size_t)t * 256;
#pragma unroll
        for (int j = 0; j < 8; ++j) {
            outv[ob + lane + 32 * j] = v4[j];
            outk[ob + lane + 32 * j] = k4[j];
        }

        // row validity: any nonzero v element across the whole row (intra-warp)
        int nz = 0;
#pragma unroll
        for (int j = 0; j < 8; ++j)
            nz |= (v4[j].x != 0.f) | (v4[j].y != 0.f) |
                  (v4[j].z != 0.f) | (v4[j].w != 0.f);
        const int valid = __any_sync(0xffffffffu, nz);

#pragma unroll
        for (int j = 0; j < 8; ++j) {
            float pd = q4[j].x * k4[j].x + q4[j].y * k4[j].y +
                       q4[j].z * k4[j].z + q4[j].w * k4[j].w;
            pd += __shfl_xor_sync(0xffffffffu, pd, 1);
            pd += __shfl_xor_sync(0xffffffffu, pd, 2);
            pd += __shfl_xor_sync(0xffffffffu, pd, 4);
            pd += __shfl_xor_sync(0xffffffffu, pd, 8);
            if (valid) {
                const float p = __expf(pd * 0.125f);   // no-max softmax (bounded logits)
                lsum[j] += p;
                acc[j].x += p * v4[j].x;
                acc[j].y += p * v4[j].y;
                acc[j].z += p * v4[j].z;
                acc[j].w += p * v4[j].w;
            }
        }
    }

    // block-level reduction in shared, then one atomic pass per block
    __shared__ float4 sacc[WPB * 256];
    __shared__ float  sl[WPB][NH];
#pragma unroll
    for (int j = 0; j < 8; ++j) {
        const int h  = 2 * j + (lane >> 4);
        const int gi = h * 16 + (lane & 15);
        sacc[wid * 256 + gi] = acc[j];
        if ((lane & 15) == 0) sl[wid][h] = lsum[j];
    }
    __syncthreads();

    const int tid = threadIdx.x;
    float4 tot = sacc[tid];
#pragma unroll
    for (int w = 1; w < WPB; ++w) {
        const float4 o = sacc[w * 256 + tid];
        tot.x += o.x; tot.y += o.y; tot.z += o.z; tot.w += o.w;
    }
    atomicAdd(&g_values[tid * 4 + 0], tot.x);
    atomicAdd(&g_values[tid * 4 + 1], tot.y);
    atomicAdd(&g_values[tid * 4 + 2], tot.z);
    atomicAdd(&g_values[tid * 4 + 3], tot.w);
    if (tid < NH) {
        float s = 0.f;
#pragma unroll
        for (int w = 0; w < WPB; ++w) s += sl[w][tid];
        atomicAdd(&g_l[tid], s);
    }
}

// ---------------- K3: output projection (split-K GEMV, atomic into d_out) ----------------
__global__ __launch_bounds__(256) void out_kernel(const float* __restrict__ Wo,
                                                  float* __restrict__ out) {
    const int j  = blockIdx.x * 256 + threadIdx.x;
    const int i0 = blockIdx.y * IPB;
    __shared__ float xs[IPB];
    if (threadIdx.x < IPB) {
        const int src = i0 + threadIdx.x;
        xs[threadIdx.x] = g_values[src] / g_l[src >> 6];   // fold softmax denom here
    }
    __syncthreads();
    float acc = 0.f;
#pragma unroll 8
    for (int i = 0; i < IPB; ++i)
        acc += xs[i] * Wo[(size_t)(i0 + i) * EMBED + j];
    atomicAdd(&out[j], acc);
}

// ---------------- launch ----------------
extern "C" void kernel_launch(void* const* d_in, const int* in_sizes, int n_in,
                              void* d_out, int out_size) {
    const float* x     = (const float*)d_in[0];
    const float* cache = (const float*)d_in[1];
    const float* Wv    = (const float*)d_in[2];
    const float* bv    = (const float*)d_in[3];
    const float* Wq    = (const float*)d_in[4];
    const float* bq    = (const float*)d_in[5];
    const float* Wk    = (const float*)d_in[6];
    const float* bk    = (const float*)d_in[7];
    const float* Wo    = (const float*)d_in[8];
    const float* bo    = (const float*)d_in[9];
    float* out = (float*)d_out;

    init_kernel<<<21, 256>>>(bq, bk, bv, bo, out);
    qkv_kernel<<<dim3(3, 4, ISPLIT), 256>>>(x, Wq, Wk, Wv);
    shift_attn_kernel<<<NBLK, 256>>>(cache, out);
    out_kernel<<<dim3(4, ISPLIT), 256>>>(Wo, out);
}

// round 7
// speedup vs baseline: 1.6463x; 1.2335x over previous
#include <cuda_runtime.h>
#include <math_constants.h>

#define EMBED   1024
#define NH      16
#define HD      64
#define CACHE   16384
#define NBLK    148               // one block per SM, grid-stride over rows
#define WPB     10                // warps per block (320 threads, 204 regs/thread budget)
#define NW      (NBLK * WPB)      // total warps = 1480
#define QSPLIT  64
#define QRPB    (EMBED / QSPLIT)  // 16 rows of W per qkv block
#define OSPLIT  64
#define ORPB    (EMBED / OSPLIT)  // 16 rows of Wo per out block

// ---------------- device scratch (no allocations allowed) ----------------
__device__ __align__(16) float g_qkv[3 * EMBED];   // [0]=q, [1]=k_i, [2]=v_i (with bias)
__device__ __align__(16) float g_values[EMBED];    // unnormalized attention output
__device__ __align__(16) float g_l[NH];            // sum-exp per head

// ---------------- K_init: zero accumulators each replay ----------------
__global__ void init_kernel(float* __restrict__ out) {
    int i = blockIdx.x * blockDim.x + threadIdx.x;   // 0..5375
    if (i < 3 * EMBED)           g_qkv[i]               = 0.f;
    else if (i < 4 * EMBED)      g_values[i - 3 * EMBED] = 0.f;
    else if (i < 5 * EMBED)      out[i - 4 * EMBED]     = 0.f;
    else if (i < 5 * EMBED + NH) g_l[i - 5 * EMBED]     = 0.f;
}

// ---------------- K0: q/k/v projections (float4 columns, MLP-8 batched loads) ----------------
__global__ __launch_bounds__(256) void qkv_kernel(const float* __restrict__ x,
                                                  const float* __restrict__ Wq,
                                                  const float* __restrict__ Wk,
                                                  const float* __restrict__ Wv,
                                                  const float* __restrict__ bq,
                                                  const float* __restrict__ bk,
                                                  const float* __restrict__ bv) {
    const int mat = blockIdx.x;                     // 0=q,1=k,2=v
    const int t   = threadIdx.x;                    // float4 column 0..255
    const int i0  = blockIdx.y * QRPB;              // input-row slice
    const float* W = (mat == 0) ? Wq : (mat == 1) ? Wk : Wv;
    const float* b = (mat == 0) ? bq : (mat == 1) ? bk : bv;

    __shared__ float xs[QRPB];
    if (t < QRPB) xs[t] = x[i0 + t];
    __syncthreads();

    const float4* W4 = reinterpret_cast<const float4*>(W);
    float4 a = make_float4(0.f, 0.f, 0.f, 0.f);
#pragma unroll
    for (int g = 0; g < QRPB; g += 8) {
        float4 w[8];
#pragma unroll
        for (int r = 0; r < 8; ++r)
            w[r] = W4[(size_t)(i0 + g + r) * 256 + t];
#pragma unroll
        for (int r = 0; r < 8; ++r) {
            const float s = xs[g + r];
            a.x += s * w[r].x; a.y += s * w[r].y;
            a.z += s * w[r].z; a.w += s * w[r].w;
        }
    }
    if (blockIdx.y == 0) {
        const float4 b4 = reinterpret_cast<const float4*>(b)[t];
        a.x += b4.x; a.y += b4.y; a.z += b4.z; a.w += b4.w;
    }
    float* dst = &g_qkv[mat * EMBED + t * 4];
    atomicAdd(dst + 0, a.x);
    atomicAdd(dst + 1, a.y);
    atomicAdd(dst + 2, a.z);
    atomicAdd(dst + 3, a.w);
}

// ---------------- K1: warp-per-row fused shift + attention (no block barriers) ----------------
__global__ __launch_bounds__(320, 1) void shift_attn_kernel(const float* __restrict__ cache,
                                                            float* __restrict__ out) {
    const int lane = threadIdx.x & 31;
    const int wid  = threadIdx.x >> 5;              // warp in block 0..9
    const int gw   = blockIdx.x * WPB + wid;        // global warp 0..1479

    const float4* cv = reinterpret_cast<const float4*>(cache);
    const float4* ck = reinterpret_cast<const float4*>(cache + (size_t)CACHE * EMBED);
    const float4* qf = reinterpret_cast<const float4*>(g_qkv);              // 256 float4
    const float4* kf = reinterpret_cast<const float4*>(g_qkv + EMBED);
    const float4* vf = reinterpret_cast<const float4*>(g_qkv + 2 * EMBED);
    float4* outv = reinterpret_cast<float4*>(out + EMBED);
    float4* outk = reinterpret_cast<float4*>(out + EMBED + (size_t)CACHE * EMBED);

    // q for this lane's 8 head-chunks (row-invariant; preload once)
    float4 q4[8];
#pragma unroll
    for (int j = 0; j < 8; ++j) q4[j] = qf[lane + 32 * j];

    float4 acc[8];
#pragma unroll
    for (int j = 0; j < 8; ++j) acc[j] = make_float4(0.f, 0.f, 0.f, 0.f);
    float lsum[8];
#pragma unroll
    for (int j = 0; j < 8; ++j) lsum[j] = 0.f;

    for (int t = gw; t < CACHE; t += NW) {
        float4 v4[8], k4[8];
        if (t == CACHE - 1) {
#pragma unroll
            for (int j = 0; j < 8; ++j) {
                v4[j] = vf[lane + 32 * j];
                k4[j] = kf[lane + 32 * j];
            }
        } else {
            const size_t base = (size_t)(t + 1) * 256;
#pragma unroll
            for (int j = 0; j < 8; ++j) {
                v4[j] = __ldcs(&cv[base + lane + 32 * j]);
                k4[j] = __ldcs(&ck[base + lane + 32 * j]);
            }
        }

        // shifted-cache writes (warp covers whole row); streaming stores
        const size_t ob = (size_t)t * 256;
#pragma unroll
        for (int j = 0; j < 8; ++j) {
            __stcs(&outv[ob + lane + 32 * j], v4[j]);
            __stcs(&outk[ob + lane + 32 * j], k4[j]);
        }

        // row validity: any nonzero v element across the whole row (intra-warp)
        int nz = 0;
#pragma unroll
        for (int j = 0; j < 8; ++j)
            nz |= (v4[j].x != 0.f) | (v4[j].y != 0.f) |
                  (v4[j].z != 0.f) | (v4[j].w != 0.f);
        const int valid = __any_sync(0xffffffffu, nz);

#pragma unroll
        for (int j = 0; j < 8; ++j) {
            float pd = q4[j].x * k4[j].x + q4[j].y * k4[j].y +
                       q4[j].z * k4[j].z + q4[j].w * k4[j].w;
            pd += __shfl_xor_sync(0xffffffffu, pd, 1);
            pd += __shfl_xor_sync(0xffffffffu, pd, 2);
            pd += __shfl_xor_sync(0xffffffffu, pd, 4);
            pd += __shfl_xor_sync(0xffffffffu, pd, 8);
            if (valid) {
                const float p = __expf(pd * 0.125f);   // no-max softmax (bounded logits)
                lsum[j] += p;
                acc[j].x += p * v4[j].x;
                acc[j].y += p * v4[j].y;
                acc[j].z += p * v4[j].z;
                acc[j].w += p * v4[j].w;
            }
        }
    }

    // block-level reduction in shared, then one atomic pass per block
    __shared__ float4 sacc[WPB * 256];
    __shared__ float  sl[WPB][NH];
#pragma unroll
    for (int j = 0; j < 8; ++j) {
        const int h  = 2 * j + (lane >> 4);
        const int gi = h * 16 + (lane & 15);
        sacc[wid * 256 + gi] = acc[j];
        if ((lane & 15) == 0) sl[wid][h] = lsum[j];
    }
    __syncthreads();

    const int tid = threadIdx.x;
    if (tid < 256) {
        float4 tot = sacc[tid];
#pragma unroll
        for (int w = 1; w < WPB; ++w) {
            const float4 o = sacc[w * 256 + tid];
            tot.x += o.x; tot.y += o.y; tot.z += o.z; tot.w += o.w;
        }
        atomicAdd(&g_values[tid * 4 + 0], tot.x);
        atomicAdd(&g_values[tid * 4 + 1], tot.y);
        atomicAdd(&g_values[tid * 4 + 2], tot.z);
        atomicAdd(&g_values[tid * 4 + 3], tot.w);
        if (tid < NH) {
            float s = 0.f;
#pragma unroll
            for (int w = 0; w < WPB; ++w) s += sl[w][tid];
            atomicAdd(&g_l[tid], s);
        }
    }
}

// ---------------- K3: output projection (float4 columns, MLP-8 batched loads) ----------------
__global__ __launch_bounds__(256) void out_kernel(const float* __restrict__ Wo,
                                                  const float* __restrict__ bo,
                                                  float* __restrict__ out) {
    const int t  = threadIdx.x;                     // float4 column 0..255
    const int i0 = blockIdx.x * ORPB;
    __shared__ float xs[ORPB];
    if (t < ORPB) {
        const int src = i0 + t;
        xs[t] = g_values[src] / g_l[src >> 6];      // fold softmax denom here
    }
    __syncthreads();

    const float4* W4 = reinterpret_cast<const float4*>(Wo);
    float4 a = make_float4(0.f, 0.f, 0.f, 0.f);
#pragma unroll
    for (int g = 0; g < ORPB; g += 8) {
        float4 w[8];
#pragma unroll
        for (int r = 0; r < 8; ++r)
            w[r] = W4[(size_t)(i0 + g + r) * 256 + t];
#pragma unroll
        for (int r = 0; r < 8; ++r) {
            const float s = xs[g + r];
            a.x += s * w[r].x; a.y += s * w[r].y;
            a.z += s * w[r].z; a.w += s * w[r].w;
        }
    }
    if (blockIdx.x == 0) {
        const float4 b4 = reinterpret_cast<const float4*>(bo)[t];
        a.x += b4.x; a.y += b4.y; a.z += b4.z; a.w += b4.w;
    }
    atomicAdd(&out[t * 4 + 0], a.x);
    atomicAdd(&out[t * 4 + 1], a.y);
    atomicAdd(&out[t * 4 + 2], a.z);
    atomicAdd(&out[t * 4 + 3], a.w);
}

// ---------------- launch ----------------
extern "C" void kernel_launch(void* const* d_in, const int* in_sizes, int n_in,
                              void* d_out, int out_size) {
    const float* x     = (const float*)d_in[0];
    const float* cache = (const float*)d_in[1];
    const float* Wv    = (const float*)d_in[2];
    const float* bv    = (const float*)d_in[3];
    const float* Wq    = (const float*)d_in[4];
    const float* bq    = (const float*)d_in[5];
    const float* Wk    = (const float*)d_in[6];
    const float* bk    = (const float*)d_in[7];
    const float* Wo    = (const float*)d_in[8];
    const float* bo    = (const float*)d_in[9];
    float* out = (float*)d_out;

    init_kernel<<<21, 256>>>(out);
    qkv_kernel<<<dim3(3, QSPLIT), 256>>>(x, Wq, Wk, Wv, bq, bk, bv);
    shift_attn_kernel<<<NBLK, 32 * WPB>>>(cache, out);
    out_kernel<<<OSPLIT, 256>>>(Wo, bo, out);
}